// round 3
// baseline (speedup 1.0000x reference)
#include <cuda_runtime.h>
#include <cstdint>
#include <math.h>

#define NROWS 260000
#define NCOLS 1024
#define NBINS 20
#define BINSZ 13000
#define NBOUND 19
#define TIECAP 256

// ---------------- static device scratch (no allocation allowed) ----------------
__device__ float         g_conf[NROWS];
__device__ unsigned char g_acc[NROWS];
__device__ int           g_hist1[65536];
__device__ int           g_hist2[NBOUND][65536];
__device__ int           g_bB[NBOUND];      // hi-bucket of boundary b
__device__ int           g_base[NBOUND];    // exclusive count before that bucket
__device__ int           g_slot[NBOUND];    // boundary -> hist2 slot
__device__ int           g_slots[NBOUND];   // slot -> hi-bucket id
__device__ int           g_nslots;
__device__ unsigned      g_tkey[NBOUND];    // full 32-bit threshold keys
__device__ int           g_cntlt[NBOUND];   // #elements with key strictly < tkey
__device__ int           g_tiecnt[NBOUND];
__device__ int           g_tielist[NBOUND][TIECAP];
__device__ double        g_bconf[NBINS];
__device__ int           g_bacc[NBINS];
__device__ int           g_is64;

// ---------------- zero scratch each launch (graph-replay safe) ----------------
__global__ void k_zero() {
    int i = blockIdx.x * 256 + threadIdx.x;
    if (i < 65536) g_hist1[i] = 0;
    int j = i - 65536;
    if (j >= 0 && j < NBOUND * 65536) ((int*)g_hist2)[j] = 0;
    if (i < NBOUND) g_tiecnt[i] = 0;
    if (i < NBINS) { g_bconf[i] = 0.0; g_bacc[i] = 0; }
}

// Detect whether labels arrived as int64 (odd 32-bit words all zero) or int32.
__global__ void k_detect(const void* __restrict__ labels) {
    if (threadIdx.x == 0 && blockIdx.x == 0) {
        const unsigned* p = (const unsigned*)labels;
        unsigned o = 0;
        for (int i = 0; i < 32; i++) o |= p[2 * i + 1];
        g_is64 = (o == 0) ? 1 : 0;
    }
}

// ---------------- heavy kernel: per-row softmax max-conf + argmax-acc ---------
// One warp per row; lane holds 32 values (8 x float4, coalesced).
// exp via FMA-only 2^f polynomial — NO MUFU (MUFU rt would cost ~2ms here).
__global__ __launch_bounds__(256) void k_rowstats(const float* __restrict__ logits,
                                                  const void* __restrict__ labels) {
    int row  = (blockIdx.x << 3) + (threadIdx.x >> 5);
    int lane = threadIdx.x & 31;
    const float4* rp = reinterpret_cast<const float4*>(logits + (size_t)row * NCOLS);

    float v[32];
#pragma unroll
    for (int s = 0; s < 8; s++) {
        float4 q = rp[(s << 5) + lane];
        v[s * 4 + 0] = q.x; v[s * 4 + 1] = q.y; v[s * 4 + 2] = q.z; v[s * 4 + 3] = q.w;
    }

    // local max + argmax (first occurrence: cols ascend within lane in (s,u))
    float m = -3.402823466e+38f;
    int   mi = NCOLS;
#pragma unroll
    for (int s = 0; s < 8; s++) {
#pragma unroll
        for (int u = 0; u < 4; u++) {
            int col = (s << 7) + (lane << 2) + u;
            float x = v[s * 4 + u];
            if (x > m) { m = x; mi = col; }
        }
    }
    // warp reduce (max, lowest index on ties) — matches jnp.argmax semantics
#pragma unroll
    for (int off = 16; off > 0; off >>= 1) {
        float m2 = __shfl_down_sync(0xffffffffu, m, off);
        int   i2 = __shfl_down_sync(0xffffffffu, mi, off);
        if (m2 > m || (m2 == m && i2 < mi)) { m = m2; mi = i2; }
    }
    m  = __shfl_sync(0xffffffffu, m, 0);
    mi = __shfl_sync(0xffffffffu, mi, 0);

    // sum exp(x - m) via 2^t poly (t = (x-m)*log2e), FMA-only
    const float L2E = 1.4426950408889634f;
    float s = 0.f;
#pragma unroll
    for (int j = 0; j < 32; j++) {
        float x = (v[j] - m) * L2E;          // <= 0
        x = fmaxf(x, -125.0f);
        float fk = x + 12582912.0f;          // round-to-nearest int via magic add
        int   k  = __float_as_int(fk) - 0x4B400000;
        float f  = x - (fk - 12582912.0f);   // f in [-0.5, 0.5]
        float p  = fmaf(1.5403530393381609e-4f, f, 1.3333558146428443e-3f);
        p = fmaf(p, f, 9.6181291076284770e-3f);
        p = fmaf(p, f, 5.5504108664821580e-2f);
        p = fmaf(p, f, 2.4022650695910070e-1f);
        p = fmaf(p, f, 6.9314718055994530e-1f);
        p = fmaf(p, f, 1.0f);
        s += __int_as_float((k + 127) << 23) * p;   // 2^k * 2^f
    }
#pragma unroll
    for (int off = 16; off > 0; off >>= 1) s += __shfl_xor_sync(0xffffffffu, s, off);

    if (lane == 0) {
        float conf = 1.0f / s;               // softmax max = 1 / sum exp(x - max)
        g_conf[row] = conf;
        long long lbl = g_is64 ? ((const long long*)labels)[row]
                               : (long long)((const int*)labels)[row];
        g_acc[row] = (mi == (int)lbl) ? 1 : 0;
        atomicAdd(&g_hist1[__float_as_uint(conf) >> 16], 1);
    }
}

// ---------------- locate boundary hi-buckets (ranks k*13000) ------------------
__global__ __launch_bounds__(1024) void k_findhi() {
    __shared__ int sc[1024];
    int t = threadIdx.x;
    int base = t << 6;
    int s = 0;
    for (int j = 0; j < 64; j++) s += g_hist1[base + j];
    sc[t] = s;
    __syncthreads();
    for (int off = 1; off < 1024; off <<= 1) {
        int x = (t >= off) ? sc[t - off] : 0;
        __syncthreads();
        sc[t] += x;
        __syncthreads();
    }
    int c = sc[t] - s;  // exclusive prefix at this thread's first bucket
    for (int j = 0; j < 64; j++) {
        int h = g_hist1[base + j];
        if (h > 0) {
            for (int b = 0; b < NBOUND; b++) {
                int R = (b + 1) * BINSZ;
                if (c < R && R <= c + h) { g_bB[b] = base + j; g_base[b] = c; }
            }
        }
        c += h;
    }
    __syncthreads();
    if (t == 0) {
        int ns = 0;
        for (int b = 0; b < NBOUND; b++) {
            int B = g_bB[b], sl = -1;
            for (int j = 0; j < ns; j++) if (g_slots[j] == B) sl = j;
            if (sl < 0) { sl = ns; g_slots[ns++] = B; }
            g_slot[b] = sl;
        }
        g_nslots = ns;
    }
}

// ---------------- low-16 histograms restricted to boundary buckets ------------
__global__ __launch_bounds__(256) void k_scatter2() {
    __shared__ int ss[NBOUND];
    __shared__ int sns;
    if (threadIdx.x == 0) sns = g_nslots;
    if (threadIdx.x < NBOUND) ss[threadIdx.x] = g_slots[threadIdx.x];
    __syncthreads();
    int i = blockIdx.x * 256 + threadIdx.x;
    if (i >= NROWS) return;
    unsigned key = __float_as_uint(g_conf[i]);
    int hi = key >> 16;
    int ns = sns;
    for (int sl = 0; sl < ns; sl++) {
        if (ss[sl] == hi) { atomicAdd(&g_hist2[sl][key & 0xFFFF], 1); break; }
    }
}

// ---------------- exact 32-bit threshold key per boundary ---------------------
__global__ __launch_bounds__(1024) void k_findlow() {
    int b = blockIdx.x;
    __shared__ int sc[1024];
    int t = threadIdx.x;
    int sl = g_slot[b];
    int rr = (b + 1) * BINSZ - 1 - g_base[b];   // in-bucket 0-based rank
    const int* h2 = g_hist2[sl];
    int base = t << 6;
    int s = 0;
    for (int j = 0; j < 64; j++) s += h2[base + j];
    sc[t] = s;
    __syncthreads();
    for (int off = 1; off < 1024; off <<= 1) {
        int x = (t >= off) ? sc[t - off] : 0;
        __syncthreads();
        sc[t] += x;
        __syncthreads();
    }
    int c = sc[t] - s;
    for (int j = 0; j < 64; j++) {
        int h = h2[base + j];
        if (h > 0 && c <= rr && rr < c + h) {
            g_tkey[b]  = ((unsigned)g_bB[b] << 16) | (unsigned)(base + j);
            g_cntlt[b] = g_base[b] + c;
        }
        c += h;
    }
}

// ---------------- per-element bin assignment + bin sums -----------------------
__global__ __launch_bounds__(256) void k_binsum() {
    __shared__ unsigned tk[NBOUND];
    __shared__ float sconf[NBINS];
    __shared__ int   sacc[NBINS];
    int t = threadIdx.x;
    if (t < NBOUND) tk[t] = g_tkey[t];
    if (t < NBINS) { sconf[t] = 0.f; sacc[t] = 0; }
    __syncthreads();
    for (int i = blockIdx.x * 256 + t; i < NROWS; i += gridDim.x * 256) {
        float cf = g_conf[i];
        unsigned key = __float_as_uint(cf);
        int cnt = 0, tied = -1;
#pragma unroll
        for (int b = 0; b < NBOUND; b++) {
            unsigned tb = tk[b];
            cnt += (tb < key);
            if (tb == key && tied < 0) tied = b;
        }
        // tied elements provisionally go below the boundary (bin = cnt = tied);
        // the finalize kernel deterministically moves the largest-index ones up,
        // matching jnp.argsort's stable tie-break exactly.
        if (tied >= 0) {
            int p = atomicAdd(&g_tiecnt[tied], 1);
            if (p < TIECAP) g_tielist[tied][p] = i;
        }
        atomicAdd(&sconf[cnt], cf);
        atomicAdd(&sacc[cnt], (int)g_acc[i]);
    }
    __syncthreads();
    if (t < NBINS) {
        atomicAdd(&g_bconf[t], (double)sconf[t]);
        atomicAdd(&g_bacc[t], sacc[t]);
    }
}

// ---------------- tie fixup + ece/mce -----------------------------------------
__global__ void k_finalize(float* __restrict__ out) {
    if (threadIdx.x != 0 || blockIdx.x != 0) return;
    double bc[NBINS];
    int    ba[NBINS];
    for (int b = 0; b < NBINS; b++) { bc[b] = g_bconf[b]; ba[b] = g_bacc[b]; }
    for (int b = 0; b < NBOUND; b++) {
        int total = g_tiecnt[b];
        int L = total < TIECAP ? total : TIECAP;
        int tie_take = (b + 1) * BINSZ - g_cntlt[b];   // tied elems staying below
        int n_move = total - tie_take;                 // tied elems moving above
        if (n_move > 0) {
            float cv = __uint_as_float(g_tkey[b]);
            for (int e = 0; e < L; e++) {
                int idx = g_tielist[b][e];
                int rd = 0;
                for (int e2 = 0; e2 < L; e2++) if (g_tielist[b][e2] > idx) rd++;
                if (rd < n_move) {   // among the n_move largest indices -> above
                    bc[b]     -= (double)cv;
                    bc[b + 1] += (double)cv;
                    int a = (int)g_acc[idx];
                    ba[b]     -= a;
                    ba[b + 1] += a;
                }
            }
        }
    }
    double ece = 0.0, mce = 0.0;
    for (int b = 0; b < NBINS; b++) {
        double ce = fabs(bc[b] - (double)ba[b]) / (double)BINSZ;
        ece += ce;
        if (ce > mce) mce = ce;
    }
    out[0] = (float)(ece / (double)NBINS);
    out[1] = (float)mce;
}

// ---------------- launch ------------------------------------------------------
extern "C" void kernel_launch(void* const* d_in, const int* in_sizes, int n_in,
                              void* d_out, int out_size) {
    const float* logits = (const float*)d_in[0];
    const void*  labels = d_in[1];
    (void)in_sizes; (void)n_in; (void)out_size;

    k_zero<<<(65536 + NBOUND * 65536 + 255) / 256, 256>>>();
    k_detect<<<1, 32>>>(labels);
    k_rowstats<<<NROWS / 8, 256>>>(logits, labels);
    k_findhi<<<1, 1024>>>();
    k_scatter2<<<(NROWS + 255) / 256, 256>>>();
    k_findlow<<<NBOUND, 1024>>>();
    k_binsum<<<512, 256>>>();
    k_finalize<<<1, 32>>>((float*)d_out);
}

// round 4
// speedup vs baseline: 1.3726x; 1.3726x over previous
#include <cuda_runtime.h>
#include <cstdint>
#include <math.h>

#define NROWS 260000
#define NCOLS 1024
#define NBINS 20
#define BINSZ 13000
#define NBOUND 19
#define TIECAP 256

// ---------------- static device scratch (no allocation allowed) ----------------
__device__ float         g_conf[NROWS];
__device__ unsigned char g_acc[NROWS];
__device__ int           g_hist1[65536];
__device__ int           g_hist2[NBOUND][65536];
__device__ int           g_bB[NBOUND];      // hi-bucket of boundary b
__device__ int           g_base[NBOUND];    // exclusive count before that bucket
__device__ int           g_slot[NBOUND];    // boundary -> hist2 slot
__device__ int           g_slots[NBOUND];   // slot -> hi-bucket id
__device__ int           g_nslots;
__device__ unsigned      g_tkey[NBOUND];    // full 32-bit threshold keys
__device__ int           g_cntlt[NBOUND];   // #elements with key strictly < tkey
__device__ int           g_tiecnt[NBOUND];
__device__ int           g_tielist[NBOUND][TIECAP];
__device__ double        g_bconf[NBINS];
__device__ int           g_bacc[NBINS];
__device__ int           g_is64;

// ---------------- packed f32x2 helpers (ptxas never auto-fuses FFMA2) ---------
typedef unsigned long long ull;

static __device__ __forceinline__ ull pk2(float a, float b) {
    ull r; asm("mov.b64 %0, {%1, %2};" : "=l"(r) : "f"(a), "f"(b)); return r;
}
static __device__ __forceinline__ float lo2(ull x) { return __uint_as_float((unsigned)x); }
static __device__ __forceinline__ float hi2(ull x) { return __uint_as_float((unsigned)(x >> 32)); }
static __device__ __forceinline__ ull fma2(ull a, ull b, ull c) {
    ull r; asm("fma.rn.f32x2 %0, %1, %2, %3;" : "=l"(r) : "l"(a), "l"(b), "l"(c)); return r;
}
static __device__ __forceinline__ ull add2(ull a, ull b) {
    ull r; asm("add.rn.f32x2 %0, %1, %2;" : "=l"(r) : "l"(a), "l"(b)); return r;
}

// ---------------- zero scratch each launch (graph-replay safe) ----------------
__global__ void k_zero() {
    int i = blockIdx.x * 256 + threadIdx.x;
    if (i < 65536) g_hist1[i] = 0;
    int j = i - 65536;
    if (j >= 0 && j < NBOUND * 65536) ((int*)g_hist2)[j] = 0;
    if (i < NBOUND) g_tiecnt[i] = 0;
    if (i < NBINS) { g_bconf[i] = 0.0; g_bacc[i] = 0; }
}

// Detect whether labels arrived as int64 (odd 32-bit words all zero) or int32.
__global__ void k_detect(const void* __restrict__ labels) {
    if (threadIdx.x == 0 && blockIdx.x == 0) {
        const unsigned* p = (const unsigned*)labels;
        unsigned o = 0;
        for (int i = 0; i < 32; i++) o |= p[2 * i + 1];
        g_is64 = (o == 0) ? 1 : 0;
    }
}

// ---------------- heavy kernel: per-row softmax max-conf + argmax-acc ---------
// One warp per row; lane holds 32 values as 16 packed f32x2 pairs.
// exp evaluated fully packed (2 elements / instruction) — no MUFU, no repack:
// ulonglong2 loads put adjacent elements in adjacent regs already.
__global__ __launch_bounds__(256) void k_rowstats(const float* __restrict__ logits,
                                                  const void* __restrict__ labels) {
    int row  = (blockIdx.x << 3) + (threadIdx.x >> 5);
    int lane = threadIdx.x & 31;
    const ulonglong2* rp = reinterpret_cast<const ulonglong2*>(logits + (size_t)row * NCOLS);

    ull w[16];
#pragma unroll
    for (int s8 = 0; s8 < 8; s8++) {
        ulonglong2 q = rp[(s8 << 5) + lane];
        w[s8 * 2]     = q.x;
        w[s8 * 2 + 1] = q.y;
    }

    // pass 1: max (FMNMX, alu pipe)
    float m = -3.402823466e+38f;
#pragma unroll
    for (int j = 0; j < 16; j++) {
        m = fmaxf(m, lo2(w[j]));
        m = fmaxf(m, hi2(w[j]));
    }
#pragma unroll
    for (int off = 16; off > 0; off >>= 1)
        m = fmaxf(m, __shfl_xor_sync(0xffffffffu, m, off));

    // pass 2: first index equal to max (matches jnp.argmax)
    int mi = NCOLS;
#pragma unroll
    for (int j = 0; j < 16; j++) {
        int colb = (j >> 1) * 128 + (lane << 2) + ((j & 1) << 1);
        if (lo2(w[j]) == m) mi = min(mi, colb);
        if (hi2(w[j]) == m) mi = min(mi, colb + 1);
    }
#pragma unroll
    for (int off = 16; off > 0; off >>= 1)
        mi = min(mi, __shfl_xor_sync(0xffffffffu, mi, off));

    // pass 3: sum exp(x - m), packed 2^t poly. t = x*L2E - m*L2E in [-17, 0].
    const float L2E = 1.4426950408889634f;
    const ull L2E2  = pk2(L2E, L2E);
    const ull MAG2  = pk2(12582912.0f, 12582912.0f);
    const ull NMAG2 = pk2(-12582912.0f, -12582912.0f);
    const ull NEG1  = pk2(-1.0f, -1.0f);
    const ull C6 = pk2(1.5403530393381609e-4f, 1.5403530393381609e-4f);
    const ull C5 = pk2(1.3333558146428443e-3f, 1.3333558146428443e-3f);
    const ull C4 = pk2(9.6181291076284770e-3f, 9.6181291076284770e-3f);
    const ull C3 = pk2(5.5504108664821580e-2f, 5.5504108664821580e-2f);
    const ull C2 = pk2(2.4022650695910070e-1f, 2.4022650695910070e-1f);
    const ull C1 = pk2(6.9314718055994530e-1f, 6.9314718055994530e-1f);
    const ull ONE2 = pk2(1.0f, 1.0f);
    float nm = -m * L2E;
    const ull NM2 = pk2(nm, nm);

    ull acc = pk2(0.f, 0.f);
#pragma unroll
    for (int j = 0; j < 16; j++) {
        ull x  = fma2(w[j], L2E2, NM2);      // (v - m) * log2e, <= 0, >= -17
        ull fk = add2(x, MAG2);              // round-to-nearest int via magic add
        ull tt = add2(fk, NMAG2);            // = round(x) as float, exact
        ull f  = fma2(tt, NEG1, x);          // f = x - round(x) in [-0.5, 0.5]
        ull p  = fma2(f, C6, C5);
        p = fma2(p, f, C4);
        p = fma2(p, f, C3);
        p = fma2(p, f, C2);
        p = fma2(p, f, C1);
        p = fma2(p, f, ONE2);
        // exponent: bits(fk) = 0x4B400000 + k; (bits<<23)+0x3F800000 == bits(2^k)
        unsigned sb0 = ((unsigned)fk)         * 0x800000u + 0x3F800000u;
        unsigned sb1 = ((unsigned)(fk >> 32)) * 0x800000u + 0x3F800000u;
        ull sc = pk2(__uint_as_float(sb0), __uint_as_float(sb1));
        acc = fma2(sc, p, acc);              // += 2^k * 2^f
    }
    float s = lo2(acc) + hi2(acc);
#pragma unroll
    for (int off = 16; off > 0; off >>= 1) s += __shfl_xor_sync(0xffffffffu, s, off);

    if (lane == 0) {
        float conf = 1.0f / s;               // softmax max = 1 / sum exp(x - max)
        g_conf[row] = conf;
        long long lbl = g_is64 ? ((const long long*)labels)[row]
                               : (long long)((const int*)labels)[row];
        g_acc[row] = (mi == (int)lbl) ? 1 : 0;
        atomicAdd(&g_hist1[__float_as_uint(conf) >> 16], 1);
    }
}

// ---------------- locate boundary hi-buckets (ranks k*13000) ------------------
// Only threads whose prefix range spans a boundary (<=19 of 1024) do pass 2,
// and the per-bucket boundary scan is a constant-division range, not a 19-loop.
__global__ __launch_bounds__(1024) void k_findhi() {
    __shared__ int sc[1024];
    int t = threadIdx.x;
    const int4* h4 = (const int4*)g_hist1;
    int s = 0;
#pragma unroll
    for (int j = 0; j < 16; j++) {
        int4 q = h4[t * 16 + j];
        s += q.x + q.y + q.z + q.w;
    }
    sc[t] = s;
    __syncthreads();
    for (int off = 1; off < 1024; off <<= 1) {
        int x = (t >= off) ? sc[t - off] : 0;
        __syncthreads();
        sc[t] += x;
        __syncthreads();
    }
    int c = sc[t] - s;  // exclusive prefix at this thread's first bucket
    if ((c + s) / BINSZ > c / BINSZ) {       // some multiple of BINSZ in (c, c+s]
        int cc = c;
        for (int j = 0; j < 64; j++) {
            int h = g_hist1[t * 64 + j];
            int bp = cc / BINSZ + 1;         // smallest b+1 with (b+1)*BINSZ > cc
            int lim = cc + h;
            while (bp <= NBOUND && bp * BINSZ <= lim) {
                g_bB[bp - 1]   = t * 64 + j;
                g_base[bp - 1] = cc;
                bp++;
            }
            cc += h;
        }
    }
    __syncthreads();
    if (t == 0) {
        int ns = 0;
        for (int b = 0; b < NBOUND; b++) {
            int B = g_bB[b], sl = -1;
            for (int j = 0; j < ns; j++) if (g_slots[j] == B) sl = j;
            if (sl < 0) { sl = ns; g_slots[ns++] = B; }
            g_slot[b] = sl;
        }
        g_nslots = ns;
    }
}

// ---------------- low-16 histograms restricted to boundary buckets ------------
__global__ __launch_bounds__(256) void k_scatter2() {
    __shared__ int ss[NBOUND];
    __shared__ int sns;
    if (threadIdx.x == 0) sns = g_nslots;
    if (threadIdx.x < NBOUND) ss[threadIdx.x] = g_slots[threadIdx.x];
    __syncthreads();
    int i = blockIdx.x * 256 + threadIdx.x;
    if (i >= NROWS) return;
    unsigned key = __float_as_uint(g_conf[i]);
    int hi = key >> 16;
    int ns = sns;
    for (int sl = 0; sl < ns; sl++) {
        if (ss[sl] == hi) { atomicAdd(&g_hist2[sl][key & 0xFFFF], 1); break; }
    }
}

// ---------------- exact 32-bit threshold key per boundary ---------------------
__global__ __launch_bounds__(1024) void k_findlow() {
    int b = blockIdx.x;
    __shared__ int sc[1024];
    int t = threadIdx.x;
    int sl = g_slot[b];
    int rr = (b + 1) * BINSZ - 1 - g_base[b];   // in-bucket 0-based rank
    const int4* h4 = (const int4*)g_hist2[sl];
    int s = 0;
#pragma unroll
    for (int j = 0; j < 16; j++) {
        int4 q = h4[t * 16 + j];
        s += q.x + q.y + q.z + q.w;
    }
    sc[t] = s;
    __syncthreads();
    for (int off = 1; off < 1024; off <<= 1) {
        int x = (t >= off) ? sc[t - off] : 0;
        __syncthreads();
        sc[t] += x;
        __syncthreads();
    }
    int c = sc[t] - s;
    if (c <= rr && rr < c + s) {             // only the owning thread walks
        const int* h2 = g_hist2[sl];
        int cc = c;
        for (int j = 0; j < 64; j++) {
            int h = h2[t * 64 + j];
            if (cc <= rr && rr < cc + h) {
                g_tkey[b]  = ((unsigned)g_bB[b] << 16) | (unsigned)(t * 64 + j);
                g_cntlt[b] = g_base[b] + cc;
            }
            cc += h;
        }
    }
}

// ---------------- per-element bin assignment + bin sums -----------------------
__global__ __launch_bounds__(256) void k_binsum() {
    __shared__ unsigned tk[NBOUND];
    __shared__ float sconf[NBINS];
    __shared__ int   sacc[NBINS];
    int t = threadIdx.x;
    if (t < NBOUND) tk[t] = g_tkey[t];
    if (t < NBINS) { sconf[t] = 0.f; sacc[t] = 0; }
    __syncthreads();
    int qi = blockIdx.x * 256 + t;           // quad index, NROWS/4 = 65000 quads
    if (qi < NROWS / 4) {
        float4 cf4 = ((const float4*)g_conf)[qi];
        uchar4 a4  = ((const uchar4*)g_acc)[qi];
        float cfs[4] = {cf4.x, cf4.y, cf4.z, cf4.w};
        int   acs[4] = {a4.x, a4.y, a4.z, a4.w};
#pragma unroll
        for (int u = 0; u < 4; u++) {
            float cf = cfs[u];
            unsigned key = __float_as_uint(cf);
            int cnt = 0, tied = -1;
#pragma unroll
            for (int b = 0; b < NBOUND; b++) {
                unsigned tb = tk[b];
                cnt += (tb < key);
                if (tb == key && tied < 0) tied = b;
            }
            // tied elements provisionally go below; finalize deterministically
            // moves the largest-index ones up (matches stable argsort).
            if (tied >= 0) {
                int p = atomicAdd(&g_tiecnt[tied], 1);
                if (p < TIECAP) g_tielist[tied][p] = qi * 4 + u;
            }
            atomicAdd(&sconf[cnt], cf);
            atomicAdd(&sacc[cnt], acs[u]);
        }
    }
    __syncthreads();
    if (t < NBINS) {
        atomicAdd(&g_bconf[t], (double)sconf[t]);
        atomicAdd(&g_bacc[t], sacc[t]);
    }
}

// ---------------- tie fixup + ece/mce -----------------------------------------
__global__ void k_finalize(float* __restrict__ out) {
    if (threadIdx.x != 0 || blockIdx.x != 0) return;
    double bc[NBINS];
    int    ba[NBINS];
    for (int b = 0; b < NBINS; b++) { bc[b] = g_bconf[b]; ba[b] = g_bacc[b]; }
    for (int b = 0; b < NBOUND; b++) {
        int total = g_tiecnt[b];
        int L = total < TIECAP ? total : TIECAP;
        int tie_take = (b + 1) * BINSZ - g_cntlt[b];   // tied elems staying below
        int n_move = total - tie_take;                 // tied elems moving above
        if (n_move > 0) {
            float cv = __uint_as_float(g_tkey[b]);
            for (int e = 0; e < L; e++) {
                int idx = g_tielist[b][e];
                int rd = 0;
                for (int e2 = 0; e2 < L; e2++) if (g_tielist[b][e2] > idx) rd++;
                if (rd < n_move) {   // among the n_move largest indices -> above
                    bc[b]     -= (double)cv;
                    bc[b + 1] += (double)cv;
                    int a = (int)g_acc[idx];
                    ba[b]     -= a;
                    ba[b + 1] += a;
                }
            }
        }
    }
    double ece = 0.0, mce = 0.0;
    for (int b = 0; b < NBINS; b++) {
        double ce = fabs(bc[b] - (double)ba[b]) / (double)BINSZ;
        ece += ce;
        if (ce > mce) mce = ce;
    }
    out[0] = (float)(ece / (double)NBINS);
    out[1] = (float)mce;
}

// ---------------- launch ------------------------------------------------------
extern "C" void kernel_launch(void* const* d_in, const int* in_sizes, int n_in,
                              void* d_out, int out_size) {
    const float* logits = (const float*)d_in[0];
    const void*  labels = d_in[1];
    (void)in_sizes; (void)n_in; (void)out_size;

    k_zero<<<(65536 + NBOUND * 65536 + 255) / 256, 256>>>();
    k_detect<<<1, 32>>>(labels);
    k_rowstats<<<NROWS / 8, 256>>>(logits, labels);
    k_findhi<<<1, 1024>>>();
    k_scatter2<<<(NROWS + 255) / 256, 256>>>();
    k_findlow<<<NBOUND, 1024>>>();
    k_binsum<<<(NROWS / 4 + 255) / 256, 256>>>();
    k_finalize<<<1, 32>>>((float*)d_out);
}

// round 5
// speedup vs baseline: 1.3782x; 1.0040x over previous
#include <cuda_runtime.h>
#include <cstdint>
#include <math.h>

#define NROWS 260000
#define NCOLS 1024
#define NBINS 20
#define BINSZ 13000
#define NBOUND 19
#define TIECAP 256

// ---------------- static device scratch (no allocation allowed) ----------------
__device__ float         g_conf[NROWS];
__device__ unsigned char g_acc[NROWS];
__device__ int           g_hist1[65536];
__device__ int           g_hist2[NBOUND][65536];
__device__ int           g_bB[NBOUND];      // hi-bucket of boundary b
__device__ int           g_base[NBOUND];    // exclusive count before that bucket
__device__ int           g_slot[NBOUND];    // boundary -> hist2 slot
__device__ int           g_slots[NBOUND];   // slot -> hi-bucket id
__device__ int           g_nslots;
__device__ unsigned      g_tkey[NBOUND];    // full 32-bit threshold keys
__device__ int           g_cntlt[NBOUND];   // #elements with key strictly < tkey
__device__ int           g_tiecnt[NBOUND];
__device__ int           g_tielist[NBOUND][TIECAP];
__device__ double        g_bconf[NBINS];
__device__ int           g_bacc[NBINS];
__device__ int           g_is64;

// ---------------- packed f32x2 helpers (ptxas never auto-fuses FFMA2) ---------
typedef unsigned long long ull;

static __device__ __forceinline__ ull pk2(float a, float b) {
    ull r; asm("mov.b64 %0, {%1, %2};" : "=l"(r) : "f"(a), "f"(b)); return r;
}
static __device__ __forceinline__ float lo2(ull x) { return __uint_as_float((unsigned)x); }
static __device__ __forceinline__ float hi2(ull x) { return __uint_as_float((unsigned)(x >> 32)); }
static __device__ __forceinline__ ull fma2(ull a, ull b, ull c) {
    ull r; asm("fma.rn.f32x2 %0, %1, %2, %3;" : "=l"(r) : "l"(a), "l"(b), "l"(c)); return r;
}
static __device__ __forceinline__ ull add2(ull a, ull b) {
    ull r; asm("add.rn.f32x2 %0, %1, %2;" : "=l"(r) : "l"(a), "l"(b)); return r;
}

// ---------------- zero scratch + label-width detect (one kernel) --------------
__global__ void k_zero(const void* __restrict__ labels) {
    int i = blockIdx.x * 256 + threadIdx.x;
    if (i < 65536) g_hist1[i] = 0;
    int j = i - 65536;
    if (j >= 0 && j < NBOUND * 65536) ((int*)g_hist2)[j] = 0;
    if (i < NBOUND) g_tiecnt[i] = 0;
    if (i < NBINS) { g_bconf[i] = 0.0; g_bacc[i] = 0; }
    if (i == 0) {
        // int64 labels -> odd 32-bit words (high halves) are all zero
        const unsigned* p = (const unsigned*)labels;
        unsigned o = 0;
        for (int q = 0; q < 32; q++) o |= p[2 * q + 1];
        g_is64 = (o == 0) ? 1 : 0;
    }
}

// ---------------- heavy kernel: per-row softmax max-conf + argmax-acc ---------
// One warp per row; lane holds 32 values as 16 packed f32x2 pairs.
// exp evaluated fully packed (2 elems/instr) — no MUFU; exponent bits built via
// shift+add (alu pipe) to keep the fma pipe free for the FFMA2 stream.
__global__ __launch_bounds__(256) void k_rowstats(const float* __restrict__ logits,
                                                  const void* __restrict__ labels) {
    int row  = (blockIdx.x << 3) + (threadIdx.x >> 5);
    int lane = threadIdx.x & 31;
    const ulonglong2* rp = reinterpret_cast<const ulonglong2*>(logits + (size_t)row * NCOLS);

    ull w[16];
#pragma unroll
    for (int s8 = 0; s8 < 8; s8++) {
        ulonglong2 q = rp[(s8 << 5) + lane];
        w[s8 * 2]     = q.x;
        w[s8 * 2 + 1] = q.y;
    }

    // pass 1: max (FMNMX, alu pipe)
    float m = -3.402823466e+38f;
#pragma unroll
    for (int j = 0; j < 16; j++) {
        m = fmaxf(m, lo2(w[j]));
        m = fmaxf(m, hi2(w[j]));
    }
#pragma unroll
    for (int off = 16; off > 0; off >>= 1)
        m = fmaxf(m, __shfl_xor_sync(0xffffffffu, m, off));

    // pass 2: first index equal to max (matches jnp.argmax)
    int mi = NCOLS;
#pragma unroll
    for (int j = 0; j < 16; j++) {
        int colb = (j >> 1) * 128 + (lane << 2) + ((j & 1) << 1);
        if (lo2(w[j]) == m) mi = min(mi, colb);
        if (hi2(w[j]) == m) mi = min(mi, colb + 1);
    }
#pragma unroll
    for (int off = 16; off > 0; off >>= 1)
        mi = min(mi, __shfl_xor_sync(0xffffffffu, mi, off));

    // pass 3: sum exp(x - m), packed 2^t poly. t = x*L2E - m*L2E in [-17, 0].
    const float L2E = 1.4426950408889634f;
    const ull L2E2  = pk2(L2E, L2E);
    const ull MAG2  = pk2(12582912.0f, 12582912.0f);
    const ull NMAG2 = pk2(-12582912.0f, -12582912.0f);
    const ull NEG1  = pk2(-1.0f, -1.0f);
    const ull C6 = pk2(1.5403530393381609e-4f, 1.5403530393381609e-4f);
    const ull C5 = pk2(1.3333558146428443e-3f, 1.3333558146428443e-3f);
    const ull C4 = pk2(9.6181291076284770e-3f, 9.6181291076284770e-3f);
    const ull C3 = pk2(5.5504108664821580e-2f, 5.5504108664821580e-2f);
    const ull C2 = pk2(2.4022650695910070e-1f, 2.4022650695910070e-1f);
    const ull C1 = pk2(6.9314718055994530e-1f, 6.9314718055994530e-1f);
    const ull ONE2 = pk2(1.0f, 1.0f);
    float nm = -m * L2E;
    const ull NM2 = pk2(nm, nm);

    ull acc = pk2(0.f, 0.f);
#pragma unroll
    for (int j = 0; j < 16; j++) {
        ull x  = fma2(w[j], L2E2, NM2);      // (v - m) * log2e, <= 0, >= -17
        ull fk = add2(x, MAG2);              // round-to-nearest int via magic add
        ull tt = add2(fk, NMAG2);            // = round(x) as float, exact
        ull f  = fma2(tt, NEG1, x);          // f = x - round(x) in [-0.5, 0.5]
        ull p  = fma2(f, C6, C5);
        p = fma2(p, f, C4);
        p = fma2(p, f, C3);
        p = fma2(p, f, C2);
        p = fma2(p, f, C1);
        p = fma2(p, f, ONE2);
        // exponent: bits(fk)=0x4B400000+k; (bits<<23)+0x3F800000 == bits(2^k)
        unsigned sb0 = (((unsigned)fk)         << 23) + 0x3F800000u;  // SHF+IADD (alu)
        unsigned sb1 = (((unsigned)(fk >> 32)) << 23) + 0x3F800000u;
        ull sc = pk2(__uint_as_float(sb0), __uint_as_float(sb1));
        acc = fma2(sc, p, acc);              // += 2^k * 2^f
    }
    float s = lo2(acc) + hi2(acc);
#pragma unroll
    for (int off = 16; off > 0; off >>= 1) s += __shfl_xor_sync(0xffffffffu, s, off);

    if (lane == 0) {
        float conf = 1.0f / s;               // softmax max = 1 / sum exp(x - max)
        g_conf[row] = conf;
        long long lbl = g_is64 ? ((const long long*)labels)[row]
                               : (long long)((const int*)labels)[row];
        g_acc[row] = (mi == (int)lbl) ? 1 : 0;
        atomicAdd(&g_hist1[__float_as_uint(conf) >> 16], 1);
    }
}

// ---------------- warp-shuffle block scan (2 barriers total) ------------------
// Returns exclusive prefix of s over the 1024-thread block.
static __device__ __forceinline__ int block_exscan_1024(int s, int* wsum) {
    int lane = threadIdx.x & 31, wid = threadIdx.x >> 5;
    int inc = s;
#pragma unroll
    for (int off = 1; off < 32; off <<= 1) {
        int v = __shfl_up_sync(0xffffffffu, inc, off);
        if (lane >= off) inc += v;
    }
    if (lane == 31) wsum[wid] = inc;
    __syncthreads();
    if (wid == 0) {
        int v = wsum[lane];
        int wi = v;
#pragma unroll
        for (int off = 1; off < 32; off <<= 1) {
            int u = __shfl_up_sync(0xffffffffu, wi, off);
            if (lane >= off) wi += u;
        }
        wsum[lane] = wi - v;                 // exclusive warp offsets
    }
    __syncthreads();
    return inc - s + wsum[wid];
}

// ---------------- locate boundary hi-buckets (ranks k*13000) ------------------
__global__ __launch_bounds__(1024) void k_findhi() {
    __shared__ int wsum[32];
    int t = threadIdx.x;
    const int4* h4 = (const int4*)g_hist1;
    int s = 0;
#pragma unroll
    for (int j = 0; j < 16; j++) {
        int4 q = h4[t * 16 + j];
        s += q.x + q.y + q.z + q.w;
    }
    int c = block_exscan_1024(s, wsum);
    if ((c + s) / BINSZ > c / BINSZ) {       // some multiple of BINSZ in (c, c+s]
        int cc = c;
        for (int j = 0; j < 64; j++) {
            int h = g_hist1[t * 64 + j];
            int bp = cc / BINSZ + 1;         // smallest b+1 with (b+1)*BINSZ > cc
            int lim = cc + h;
            while (bp <= NBOUND && bp * BINSZ <= lim) {
                g_bB[bp - 1]   = t * 64 + j;
                g_base[bp - 1] = cc;
                bp++;
            }
            cc += h;
        }
    }
    __syncthreads();
    if (t == 0) {
        int ns = 0;
        for (int b = 0; b < NBOUND; b++) {
            int B = g_bB[b], sl = -1;
            for (int j = 0; j < ns; j++) if (g_slots[j] == B) sl = j;
            if (sl < 0) { sl = ns; g_slots[ns++] = B; }
            g_slot[b] = sl;
        }
        g_nslots = ns;
    }
}

// ---------------- low-16 histograms restricted to boundary buckets ------------
__global__ __launch_bounds__(256) void k_scatter2() {
    __shared__ int ss[NBOUND];
    __shared__ int sns;
    if (threadIdx.x == 0) sns = g_nslots;
    if (threadIdx.x < NBOUND) ss[threadIdx.x] = g_slots[threadIdx.x];
    __syncthreads();
    int qi = blockIdx.x * 256 + threadIdx.x;
    if (qi >= NROWS / 4) return;
    float4 cf4 = ((const float4*)g_conf)[qi];
    float cfs[4] = {cf4.x, cf4.y, cf4.z, cf4.w};
    int ns = sns;
#pragma unroll
    for (int u = 0; u < 4; u++) {
        unsigned key = __float_as_uint(cfs[u]);
        int hi = key >> 16;
        for (int sl = 0; sl < ns; sl++) {
            if (ss[sl] == hi) { atomicAdd(&g_hist2[sl][key & 0xFFFF], 1); break; }
        }
    }
}

// ---------------- exact 32-bit threshold key per boundary ---------------------
__global__ __launch_bounds__(1024) void k_findlow() {
    __shared__ int wsum[32];
    int b = blockIdx.x;
    int t = threadIdx.x;
    int sl = g_slot[b];
    int rr = (b + 1) * BINSZ - 1 - g_base[b];   // in-bucket 0-based rank
    const int4* h4 = (const int4*)g_hist2[sl];
    int s = 0;
#pragma unroll
    for (int j = 0; j < 16; j++) {
        int4 q = h4[t * 16 + j];
        s += q.x + q.y + q.z + q.w;
    }
    int c = block_exscan_1024(s, wsum);
    if (c <= rr && rr < c + s) {             // only the owning thread walks
        const int* h2 = g_hist2[sl];
        int cc = c;
        for (int j = 0; j < 64; j++) {
            int h = h2[t * 64 + j];
            if (cc <= rr && rr < cc + h) {
                g_tkey[b]  = ((unsigned)g_bB[b] << 16) | (unsigned)(t * 64 + j);
                g_cntlt[b] = g_base[b] + cc;
            }
            cc += h;
        }
    }
}

// ---------------- per-element bin assignment + bin sums -----------------------
__global__ __launch_bounds__(256) void k_binsum() {
    __shared__ unsigned tk[NBOUND];
    __shared__ float sconf[NBINS];
    __shared__ int   sacc[NBINS];
    int t = threadIdx.x;
    if (t < NBOUND) tk[t] = g_tkey[t];
    if (t < NBINS) { sconf[t] = 0.f; sacc[t] = 0; }
    __syncthreads();
    int qi = blockIdx.x * 256 + t;           // quad index, NROWS/4 = 65000 quads
    if (qi < NROWS / 4) {
        float4 cf4 = ((const float4*)g_conf)[qi];
        uchar4 a4  = ((const uchar4*)g_acc)[qi];
        float cfs[4] = {cf4.x, cf4.y, cf4.z, cf4.w};
        int   acs[4] = {a4.x, a4.y, a4.z, a4.w};
#pragma unroll
        for (int u = 0; u < 4; u++) {
            float cf = cfs[u];
            unsigned key = __float_as_uint(cf);
            int cnt = 0, tied = -1;
#pragma unroll
            for (int b = 0; b < NBOUND; b++) {
                unsigned tb = tk[b];
                cnt += (tb < key);
                if (tb == key && tied < 0) tied = b;
            }
            // tied elements provisionally go below; finalize deterministically
            // moves the largest-index ones up (matches stable argsort).
            if (tied >= 0) {
                int p = atomicAdd(&g_tiecnt[tied], 1);
                if (p < TIECAP) g_tielist[tied][p] = qi * 4 + u;
            }
            atomicAdd(&sconf[cnt], cf);
            atomicAdd(&sacc[cnt], acs[u]);
        }
    }
    __syncthreads();
    if (t < NBINS) {
        atomicAdd(&g_bconf[t], (double)sconf[t]);
        atomicAdd(&g_bacc[t], sacc[t]);
    }
}

// ---------------- tie fixup + ece/mce -----------------------------------------
__global__ void k_finalize(float* __restrict__ out) {
    if (threadIdx.x != 0 || blockIdx.x != 0) return;
    double bc[NBINS];
    int    ba[NBINS];
    for (int b = 0; b < NBINS; b++) { bc[b] = g_bconf[b]; ba[b] = g_bacc[b]; }
    for (int b = 0; b < NBOUND; b++) {
        int total = g_tiecnt[b];
        int L = total < TIECAP ? total : TIECAP;
        int tie_take = (b + 1) * BINSZ - g_cntlt[b];   // tied elems staying below
        int n_move = total - tie_take;                 // tied elems moving above
        if (n_move > 0) {
            float cv = __uint_as_float(g_tkey[b]);
            for (int e = 0; e < L; e++) {
                int idx = g_tielist[b][e];
                int rd = 0;
                for (int e2 = 0; e2 < L; e2++) if (g_tielist[b][e2] > idx) rd++;
                if (rd < n_move) {   // among the n_move largest indices -> above
                    bc[b]     -= (double)cv;
                    bc[b + 1] += (double)cv;
                    int a = (int)g_acc[idx];
                    ba[b]     -= a;
                    ba[b + 1] += a;
                }
            }
        }
    }
    double ece = 0.0, mce = 0.0;
    for (int b = 0; b < NBINS; b++) {
        double ce = fabs(bc[b] - (double)ba[b]) / (double)BINSZ;
        ece += ce;
        if (ce > mce) mce = ce;
    }
    out[0] = (float)(ece / (double)NBINS);
    out[1] = (float)mce;
}

// ---------------- launch ------------------------------------------------------
extern "C" void kernel_launch(void* const* d_in, const int* in_sizes, int n_in,
                              void* d_out, int out_size) {
    const float* logits = (const float*)d_in[0];
    const void*  labels = d_in[1];
    (void)in_sizes; (void)n_in; (void)out_size;

    k_zero<<<(65536 + NBOUND * 65536 + 255) / 256, 256>>>(labels);
    k_rowstats<<<NROWS / 8, 256>>>(logits, labels);
    k_findhi<<<1, 1024>>>();
    k_scatter2<<<(NROWS / 4 + 255) / 256, 256>>>();
    k_findlow<<<NBOUND, 1024>>>();
    k_binsum<<<(NROWS / 4 + 255) / 256, 256>>>();
    k_finalize<<<1, 32>>>((float*)d_out);
}